// round 3
// baseline (speedup 1.0000x reference)
#include <cuda_runtime.h>
#include <cuda_bf16.h>
#include <cstddef>

#define N_NODES 100000
#define N_EDGES 3200000
#define NQUAD   32          // 128 floats = 32 float4 per node row

// ---------------- scratch (static __device__, allowed) ----------------
__device__ int    g_edeg[N_NODES];
__device__ float  g_dinv[N_NODES];
__device__ int    g_rowptr[N_NODES + 1];
__device__ int    g_cursor[N_NODES];
__device__ int    g_col[N_EDGES];
__device__ float4 g_h  [(size_t)N_NODES * NQUAD];   // scaled GEMM output  g = (x@W)*dinv
__device__ float4 g_buf[(size_t)N_NODES * NQUAD];   // inter-layer activations
__device__ int    g_bsum[128];
__device__ int    g_boff[128];

static __device__ __forceinline__ int clampi(int v, int lo, int hi) {
    return v < lo ? lo : (v > hi ? hi : v);
}

// ---------------- preprocessing: degree / CSR ----------------
__global__ void k_zero_deg() {
    int i = blockIdx.x * blockDim.x + threadIdx.x;
    if (i < N_NODES) g_edeg[i] = 0;
}

// edge_index is int32 (JAX x64 disabled -> jnp.int64 silently lowers to int32)
__global__ void k_hist(const int* __restrict__ ei) {
    int e = blockIdx.x * blockDim.x + threadIdx.x;
    if (e < N_EDGES) {
        int d = clampi(ei[N_EDGES + e], 0, N_NODES - 1);
        atomicAdd(&g_edeg[d], 1);
    }
}

// block-level exclusive scan (1024 elems per block), Hillis-Steele
__global__ void k_scan1() {
    __shared__ int sh[1024];
    int i = blockIdx.x * 1024 + threadIdx.x;
    int v = (i < N_NODES) ? g_edeg[i] : 0;
    sh[threadIdx.x] = v;
    __syncthreads();
#pragma unroll
    for (int off = 1; off < 1024; off <<= 1) {
        int t = (threadIdx.x >= off) ? sh[threadIdx.x - off] : 0;
        __syncthreads();
        sh[threadIdx.x] += t;
        __syncthreads();
    }
    if (i < N_NODES) g_rowptr[i] = sh[threadIdx.x] - v;  // exclusive
    if (threadIdx.x == 1023) g_bsum[blockIdx.x] = sh[1023];
}

__global__ void k_scan2(int nblk) {
    if (threadIdx.x == 0) {
        int acc = 0;
        for (int b = 0; b < nblk; b++) { g_boff[b] = acc; acc += g_bsum[b]; }
    }
}

__global__ void k_scan3() {
    int i = blockIdx.x * blockDim.x + threadIdx.x;
    if (i < N_NODES) {
        int rp = g_rowptr[i] + g_boff[i >> 10];
        g_rowptr[i] = rp;
        g_cursor[i] = rp;
        g_dinv[i]   = rsqrtf((float)(g_edeg[i] + 1));   // +1 self loop, always > 0
    }
    if (i == 0) g_rowptr[N_NODES] = N_EDGES;
}

__global__ void k_scatter(const int* __restrict__ ei) {
    int e = blockIdx.x * blockDim.x + threadIdx.x;
    if (e < N_EDGES) {
        int s = clampi(ei[e], 0, N_NODES - 1);
        int d = clampi(ei[N_EDGES + e], 0, N_NODES - 1);
        int p = atomicAdd(&g_cursor[d], 1);
        if (p >= 0 && p < N_EDGES) g_col[p] = s;
    }
}

// ---------------- GEMM: g_h[r] = (A[r] @ W) * dinv[r] ----------------
// FIRST: A = Aext (harness x buffer). !FIRST: A = g_buf symbol.
// BM=64, BN=128, BK=32, 256 threads, 8x4 per thread.
template <bool FIRST>
__global__ __launch_bounds__(256) void k_gemm_scale(const float* __restrict__ Aext,
                                                    const float* __restrict__ W) {
    __shared__ float As[64][32];
    __shared__ float Bs[32][128];

    int m0  = blockIdx.x * 64;
    int tid = threadIdx.x;
    int tx  = tid & 31;   // N dir (x4)
    int ty  = tid >> 5;   // M dir (x8)

    float acc[8][4];
#pragma unroll
    for (int m = 0; m < 8; m++)
#pragma unroll
        for (int n = 0; n < 4; n++) acc[m][n] = 0.f;

    const float4* A4ext = reinterpret_cast<const float4*>(Aext);
    const float4* W4    = reinterpret_cast<const float4*>(W);

    for (int kk = 0; kk < 128; kk += 32) {
        // A tile: 64 rows x 8 quads = 512 float4, 2 per thread
#pragma unroll
        for (int j = 0; j < 2; j++) {
            int i = tid + j * 256;
            int r = i >> 3, q = i & 7;
            int row = m0 + r;
            float4 v = make_float4(0.f, 0.f, 0.f, 0.f);
            if (row < N_NODES) {
                size_t idx = (size_t)row * NQUAD + (kk >> 2) + q;
                v = FIRST ? A4ext[idx] : g_buf[idx];
            }
            *reinterpret_cast<float4*>(&As[r][q * 4]) = v;
        }
        // W tile: 32 rows x 32 quads = 1024 float4, 4 per thread
#pragma unroll
        for (int j = 0; j < 4; j++) {
            int i = tid + j * 256;
            int r = i >> 5, q = i & 31;
            *reinterpret_cast<float4*>(&Bs[r][q * 4]) = W4[(size_t)(kk + r) * 32 + q];
        }
        __syncthreads();

#pragma unroll
        for (int k = 0; k < 32; k++) {
            float4 bv = *reinterpret_cast<const float4*>(&Bs[k][tx * 4]); // 16B/lane, conflict-free
#pragma unroll
            for (int m = 0; m < 8; m++) {
                float a = As[ty * 8 + m][k];   // warp-broadcast
                acc[m][0] += a * bv.x;
                acc[m][1] += a * bv.y;
                acc[m][2] += a * bv.z;
                acc[m][3] += a * bv.w;
            }
        }
        __syncthreads();
    }

#pragma unroll
    for (int m = 0; m < 8; m++) {
        int row = m0 + ty * 8 + m;
        if (row < N_NODES) {
            float dv = g_dinv[row];
            float4 o;
            o.x = acc[m][0] * dv; o.y = acc[m][1] * dv;
            o.z = acc[m][2] * dv; o.w = acc[m][3] * dv;
            g_h[(size_t)row * NQUAD + tx] = o;
        }
    }
}

// ---------------- aggregation: warp per node ----------------
// out[d] = relu( dinv[d] * (g[d] + sum_{s in N(d)} g[s]) + b )
// LAST: write harness d_out. !LAST: write g_buf symbol.
template <bool LAST>
__global__ __launch_bounds__(256) void k_agg(const float* __restrict__ bias,
                                             float* __restrict__ outExt) {
    int gw   = (blockIdx.x * blockDim.x + threadIdx.x) >> 5;
    int lane = threadIdx.x & 31;
    if (gw >= N_NODES) return;

    float4 acc = g_h[(size_t)gw * NQUAD + lane];     // self-loop term
    int beg = g_rowptr[gw], end = g_rowptr[gw + 1];

    for (int j = beg; j < end; j += 32) {
        int idx = (j + lane < end) ? g_col[j + lane] : 0;
        int cnt = min(32, end - j);
        for (int t = 0; t < cnt; t++) {
            int s = __shfl_sync(0xffffffffu, idx, t);
            float4 v = g_h[(size_t)s * NQUAD + lane];
            acc.x += v.x; acc.y += v.y; acc.z += v.z; acc.w += v.w;
        }
    }

    float dv  = g_dinv[gw];
    float4 bb = reinterpret_cast<const float4*>(bias)[lane];
    float4 o;
    o.x = fmaxf(acc.x * dv + bb.x, 0.f);
    o.y = fmaxf(acc.y * dv + bb.y, 0.f);
    o.z = fmaxf(acc.z * dv + bb.z, 0.f);
    o.w = fmaxf(acc.w * dv + bb.w, 0.f);
    if (LAST) {
        reinterpret_cast<float4*>(outExt)[(size_t)gw * NQUAD + lane] = o;
    } else {
        g_buf[(size_t)gw * NQUAD + lane] = o;
    }
}

// ---------------- launch ----------------
extern "C" void kernel_launch(void* const* d_in, const int* in_sizes, int n_in,
                              void* d_out, int out_size) {
    const float* x  = (const float*)d_in[0];
    const int*   ei = (const int*)d_in[1];          // int32 edge_index (JAX x64 off)
    const float* W0 = (const float*)d_in[2];
    const float* b0 = (const float*)d_in[3];
    const float* W1 = (const float*)d_in[4];
    const float* b1 = (const float*)d_in[5];
    const float* W2 = (const float*)d_in[6];
    const float* b2 = (const float*)d_in[7];
    float* out = (float*)d_out;

    const int nodeBlocks = (N_NODES + 255) / 256;
    const int edgeBlocks = (N_EDGES + 255) / 256;
    const int scanBlocks = (N_NODES + 1023) / 1024;   // 98
    const int gemmBlocks = (N_NODES + 63) / 64;       // 1563
    const int aggBlocks  = (N_NODES * 32 + 255) / 256;

    // CSR build (recomputed every call: deterministic work)
    k_zero_deg<<<nodeBlocks, 256>>>();
    k_hist<<<edgeBlocks, 256>>>(ei);
    k_scan1<<<scanBlocks, 1024>>>();
    k_scan2<<<1, 32>>>(scanBlocks);
    k_scan3<<<nodeBlocks, 256>>>();
    k_scatter<<<edgeBlocks, 256>>>(ei);

    // layer 0
    k_gemm_scale<true ><<<gemmBlocks, 256>>>(x, W0);
    k_agg       <false><<<aggBlocks, 256>>>(b0, nullptr);
    // layer 1
    k_gemm_scale<false><<<gemmBlocks, 256>>>(nullptr, W1);
    k_agg       <false><<<aggBlocks, 256>>>(b1, nullptr);
    // layer 2
    k_gemm_scale<false><<<gemmBlocks, 256>>>(nullptr, W2);
    k_agg       <true ><<<aggBlocks, 256>>>(b2, out);
}

// round 4
// speedup vs baseline: 1.2036x; 1.2036x over previous
#include <cuda_runtime.h>
#include <cuda_bf16.h>
#include <cstddef>
#include <cstdint>

#define N_NODES 100000
#define N_EDGES 3200000
#define NQUAD   32          // 128 floats = 32 float4 per node row

// ---------------- scratch (static __device__, allowed) ----------------
__device__ int    g_edeg[N_NODES];
__device__ float  g_dinv[N_NODES];
__device__ int    g_rowptr[N_NODES + 1];
__device__ int    g_cursor[N_NODES];
__device__ int    g_col[N_EDGES];
__device__ float4 g_h  [(size_t)N_NODES * NQUAD];   // scaled GEMM output  g = (x@W)*dinv
__device__ float4 g_buf[(size_t)N_NODES * NQUAD];   // inter-layer activations
__device__ int    g_bsum[128];
__device__ int    g_boff[128];

static __device__ __forceinline__ int clampi(int v, int lo, int hi) {
    return v < lo ? lo : (v > hi ? hi : v);
}

static __device__ __forceinline__ uint32_t f2tf32(float f) {
    uint32_t r;
    asm("cvt.rna.tf32.f32 %0, %1;" : "=r"(r) : "f"(f));
    return r;
}

static __device__ __forceinline__ void mma_tf32(float* c, const uint32_t* a,
                                                uint32_t b0, uint32_t b1) {
    asm volatile(
        "mma.sync.aligned.m16n8k8.row.col.f32.tf32.tf32.f32 "
        "{%0,%1,%2,%3}, {%4,%5,%6,%7}, {%8,%9}, {%0,%1,%2,%3};\n"
        : "+f"(c[0]), "+f"(c[1]), "+f"(c[2]), "+f"(c[3])
        : "r"(a[0]), "r"(a[1]), "r"(a[2]), "r"(a[3]), "r"(b0), "r"(b1));
}

// ---------------- preprocessing: degree / CSR ----------------
__global__ void k_zero_deg() {
    int i = blockIdx.x * blockDim.x + threadIdx.x;
    if (i < N_NODES) g_edeg[i] = 0;
}

// edge_index is int32
__global__ void k_hist(const int* __restrict__ ei) {
    int e = blockIdx.x * blockDim.x + threadIdx.x;
    if (e < N_EDGES) {
        int d = clampi(ei[N_EDGES + e], 0, N_NODES - 1);
        atomicAdd(&g_edeg[d], 1);
    }
}

// block-level exclusive scan (1024 elems per block), Hillis-Steele
__global__ void k_scan1() {
    __shared__ int sh[1024];
    int i = blockIdx.x * 1024 + threadIdx.x;
    int v = (i < N_NODES) ? g_edeg[i] : 0;
    sh[threadIdx.x] = v;
    __syncthreads();
#pragma unroll
    for (int off = 1; off < 1024; off <<= 1) {
        int t = (threadIdx.x >= off) ? sh[threadIdx.x - off] : 0;
        __syncthreads();
        sh[threadIdx.x] += t;
        __syncthreads();
    }
    if (i < N_NODES) g_rowptr[i] = sh[threadIdx.x] - v;  // exclusive
    if (threadIdx.x == 1023) g_bsum[blockIdx.x] = sh[1023];
}

// parallel exclusive scan of the <=128 block sums (was a 9us serial loop)
__global__ void k_scan2(int nblk) {
    __shared__ int sh[128];
    int v = (threadIdx.x < nblk) ? g_bsum[threadIdx.x] : 0;
    sh[threadIdx.x] = v;
    __syncthreads();
#pragma unroll
    for (int off = 1; off < 128; off <<= 1) {
        int t = (threadIdx.x >= off) ? sh[threadIdx.x - off] : 0;
        __syncthreads();
        sh[threadIdx.x] += t;
        __syncthreads();
    }
    if (threadIdx.x < nblk) g_boff[threadIdx.x] = sh[threadIdx.x] - v;
}

__global__ void k_scan3() {
    int i = blockIdx.x * blockDim.x + threadIdx.x;
    if (i < N_NODES) {
        int rp = g_rowptr[i] + g_boff[i >> 10];
        g_rowptr[i] = rp;
        g_cursor[i] = rp;
        g_dinv[i]   = rsqrtf((float)(g_edeg[i] + 1));   // +1 self loop, always > 0
    }
    if (i == 0) g_rowptr[N_NODES] = N_EDGES;
}

__global__ void k_scatter(const int* __restrict__ ei) {
    int e = blockIdx.x * blockDim.x + threadIdx.x;
    if (e < N_EDGES) {
        int s = clampi(ei[e], 0, N_NODES - 1);
        int d = clampi(ei[N_EDGES + e], 0, N_NODES - 1);
        int p = atomicAdd(&g_cursor[d], 1);
        if (p >= 0 && p < N_EDGES) g_col[p] = s;
    }
}

// ---------------- TF32 tensor-core GEMM: g_h[r] = (A[r] @ W) * dinv[r] ----------------
// BM=128, BN=128, BK=32. 256 threads = 8 warps in 4(m) x 2(n); warp tile 32x64.
// mma.sync.m16n8k8 tf32: per warp 2 m-frags x 8 n-frags.
template <bool FIRST>
__global__ __launch_bounds__(256) void k_gemm_tf32(const float* __restrict__ Aext,
                                                   const float* __restrict__ W) {
    __shared__ uint32_t As[128][36];   // pad 36: bank = gid*4+tig, conflict-free
    __shared__ uint32_t Bs[32][132];   // pad 132: bank = tig*4+gid, conflict-free

    const int m0   = blockIdx.x * 128;
    const int tid  = threadIdx.x;
    const int w    = tid >> 5, lane = tid & 31;
    const int wm   = w & 3;            // 0..3 -> row base wm*32
    const int wn   = w >> 2;           // 0..1 -> col base wn*64
    const int gid  = lane >> 2, tig = lane & 3;

    float acc[2][8][4] = {};

    const float4* A4 = reinterpret_cast<const float4*>(Aext);
    const float4* W4 = reinterpret_cast<const float4*>(W);

    for (int kk = 0; kk < 128; kk += 32) {
        // A tile: 128 rows x 8 quads = 1024 float4, 4 per thread
#pragma unroll
        for (int j = 0; j < 4; j++) {
            int i = tid + j * 256;
            int r = i >> 3, q = i & 7;
            int row = m0 + r;
            float4 v = make_float4(0.f, 0.f, 0.f, 0.f);
            if (row < N_NODES) {
                size_t idx = (size_t)row * NQUAD + (kk >> 2) + q;
                v = FIRST ? A4[idx] : g_buf[idx];
            }
            As[r][q * 4 + 0] = f2tf32(v.x);
            As[r][q * 4 + 1] = f2tf32(v.y);
            As[r][q * 4 + 2] = f2tf32(v.z);
            As[r][q * 4 + 3] = f2tf32(v.w);
        }
        // B tile: 32 rows x 32 quads = 1024 float4, 4 per thread
#pragma unroll
        for (int j = 0; j < 4; j++) {
            int i = tid + j * 256;
            int r = i >> 5, q = i & 31;
            float4 v = W4[(size_t)(kk + r) * NQUAD + q];
            Bs[r][q * 4 + 0] = f2tf32(v.x);
            Bs[r][q * 4 + 1] = f2tf32(v.y);
            Bs[r][q * 4 + 2] = f2tf32(v.z);
            Bs[r][q * 4 + 3] = f2tf32(v.w);
        }
        __syncthreads();

#pragma unroll
        for (int k8 = 0; k8 < 4; k8++) {
            const int kb = k8 * 8;
            uint32_t af[2][4];
#pragma unroll
            for (int fm = 0; fm < 2; fm++) {
                int rb = wm * 32 + fm * 16 + gid;
                af[fm][0] = As[rb    ][kb + tig];
                af[fm][1] = As[rb + 8][kb + tig];
                af[fm][2] = As[rb    ][kb + tig + 4];
                af[fm][3] = As[rb + 8][kb + tig + 4];
            }
#pragma unroll
            for (int fn = 0; fn < 8; fn++) {
                int cn = wn * 64 + fn * 8 + gid;
                uint32_t b0 = Bs[kb + tig    ][cn];
                uint32_t b1 = Bs[kb + tig + 4][cn];
                mma_tf32(acc[0][fn], af[0], b0, b1);
                mma_tf32(acc[1][fn], af[1], b0, b1);
            }
        }
        __syncthreads();
    }

    // epilogue: scale rows by dinv, store float2 pairs
    float2* H2 = reinterpret_cast<float2*>(g_h);
#pragma unroll
    for (int fm = 0; fm < 2; fm++) {
        int r0 = m0 + wm * 32 + fm * 16 + gid;
        int r1 = r0 + 8;
        float d0 = (r0 < N_NODES) ? g_dinv[r0] : 0.f;
        float d1 = (r1 < N_NODES) ? g_dinv[r1] : 0.f;
#pragma unroll
        for (int fn = 0; fn < 8; fn++) {
            int c = wn * 64 + fn * 8 + tig * 2;
            if (r0 < N_NODES)
                H2[((size_t)r0 * 128 + c) >> 1] =
                    make_float2(acc[fm][fn][0] * d0, acc[fm][fn][1] * d0);
            if (r1 < N_NODES)
                H2[((size_t)r1 * 128 + c) >> 1] =
                    make_float2(acc[fm][fn][2] * d1, acc[fm][fn][3] * d1);
        }
    }
}

// ---------------- aggregation: warp per node, 8-deep gather pipeline ----------------
// out[d] = relu( dinv[d] * (g[d] + sum_{s in N(d)} g[s]) + b )
template <bool LAST>
__global__ __launch_bounds__(256) void k_agg(const float* __restrict__ bias,
                                             float* __restrict__ outExt) {
    int gw   = (blockIdx.x * blockDim.x + threadIdx.x) >> 5;
    int lane = threadIdx.x & 31;
    if (gw >= N_NODES) return;

    float4 acc = g_h[(size_t)gw * NQUAD + lane];     // self-loop term
    const int beg = g_rowptr[gw], end = g_rowptr[gw + 1];

    for (int j = beg; j < end; j += 32) {
        int jl  = j + lane;
        int idx = (jl < end) ? g_col[jl] : 0;
        int cnt = min(32, end - j);
        int t = 0;
        for (; t + 8 <= cnt; t += 8) {           // 8 independent gathers in flight
            float4 v[8];
#pragma unroll
            for (int u = 0; u < 8; u++) {
                int s = __shfl_sync(0xffffffffu, idx, t + u);
                v[u] = g_h[(size_t)s * NQUAD + lane];
            }
#pragma unroll
            for (int u = 0; u < 8; u++) {
                acc.x += v[u].x; acc.y += v[u].y; acc.z += v[u].z; acc.w += v[u].w;
            }
        }
        for (; t < cnt; t++) {
            int s = __shfl_sync(0xffffffffu, idx, t);
            float4 v = g_h[(size_t)s * NQUAD + lane];
            acc.x += v.x; acc.y += v.y; acc.z += v.z; acc.w += v.w;
        }
    }

    float dv  = g_dinv[gw];
    float4 bb = reinterpret_cast<const float4*>(bias)[lane];
    float4 o;
    o.x = fmaxf(acc.x * dv + bb.x, 0.f);
    o.y = fmaxf(acc.y * dv + bb.y, 0.f);
    o.z = fmaxf(acc.z * dv + bb.z, 0.f);
    o.w = fmaxf(acc.w * dv + bb.w, 0.f);
    if (LAST) {
        reinterpret_cast<float4*>(outExt)[(size_t)gw * NQUAD + lane] = o;
    } else {
        g_buf[(size_t)gw * NQUAD + lane] = o;
    }
}

// ---------------- launch ----------------
extern "C" void kernel_launch(void* const* d_in, const int* in_sizes, int n_in,
                              void* d_out, int out_size) {
    const float* x  = (const float*)d_in[0];
    const int*   ei = (const int*)d_in[1];          // int32 edge_index
    const float* W0 = (const float*)d_in[2];
    const float* b0 = (const float*)d_in[3];
    const float* W1 = (const float*)d_in[4];
    const float* b1 = (const float*)d_in[5];
    const float* W2 = (const float*)d_in[6];
    const float* b2 = (const float*)d_in[7];
    float* out = (float*)d_out;

    const int nodeBlocks = (N_NODES + 255) / 256;
    const int edgeBlocks = (N_EDGES + 255) / 256;
    const int scanBlocks = (N_NODES + 1023) / 1024;   // 98
    const int gemmBlocks = (N_NODES + 127) / 128;     // 782
    const int aggBlocks  = (N_NODES * 32 + 255) / 256;

    // CSR build (recomputed every call: deterministic work)
    k_zero_deg<<<nodeBlocks, 256>>>();
    k_hist<<<edgeBlocks, 256>>>(ei);
    k_scan1<<<scanBlocks, 1024>>>();
    k_scan2<<<1, 128>>>(scanBlocks);
    k_scan3<<<nodeBlocks, 256>>>();
    k_scatter<<<edgeBlocks, 256>>>(ei);

    // layer 0
    k_gemm_tf32<true ><<<gemmBlocks, 256>>>(x, W0);
    k_agg      <false><<<aggBlocks, 256>>>(b0, nullptr);
    // layer 1
    k_gemm_tf32<false><<<gemmBlocks, 256>>>(nullptr, W1);
    k_agg      <false><<<aggBlocks, 256>>>(b1, nullptr);
    // layer 2
    k_gemm_tf32<false><<<gemmBlocks, 256>>>(nullptr, W2);
    k_agg      <true ><<<aggBlocks, 256>>>(b2, out);
}

// round 5
// speedup vs baseline: 1.2754x; 1.0596x over previous
#include <cuda_runtime.h>
#include <cuda_fp16.h>
#include <cuda_bf16.h>
#include <cstddef>
#include <cstdint>

#define N_NODES 100000
#define N_EDGES 3200000
#define NQUAD   32          // 128 floats = 32 float4 per node row

// ---------------- scratch (static __device__, allowed) ----------------
__device__ int     g_edeg[N_NODES];
__device__ float   g_dinv[N_NODES];
__device__ int     g_rowptr[N_NODES + 1];
__device__ int     g_cursor[N_NODES];
__device__ int     g_col[N_EDGES];
__device__ __half2 g_h  [(size_t)N_NODES * 64];     // fp16 scaled GEMM output (256 B/row)
__device__ float4  g_buf[(size_t)N_NODES * NQUAD];  // inter-layer activations (fp32)
__device__ int     g_bsum[128];
__device__ int     g_boff[128];

static __device__ __forceinline__ int clampi(int v, int lo, int hi) {
    return v < lo ? lo : (v > hi ? hi : v);
}

static __device__ __forceinline__ uint32_t f2tf32(float f) {
    uint32_t r;
    asm("cvt.rna.tf32.f32 %0, %1;" : "=r"(r) : "f"(f));
    return r;
}

static __device__ __forceinline__ void mma_tf32(float* c, const uint32_t* a,
                                                uint32_t b0, uint32_t b1) {
    asm volatile(
        "mma.sync.aligned.m16n8k8.row.col.f32.tf32.tf32.f32 "
        "{%0,%1,%2,%3}, {%4,%5,%6,%7}, {%8,%9}, {%0,%1,%2,%3};\n"
        : "+f"(c[0]), "+f"(c[1]), "+f"(c[2]), "+f"(c[3])
        : "r"(a[0]), "r"(a[1]), "r"(a[2]), "r"(a[3]), "r"(b0), "r"(b1));
}

// ---------------- preprocessing: degree / CSR ----------------
__global__ void k_zero_deg() {
    int i = blockIdx.x * blockDim.x + threadIdx.x;
    if (i < N_NODES) g_edeg[i] = 0;
}

__global__ void k_hist(const int* __restrict__ ei) {
    int e = blockIdx.x * blockDim.x + threadIdx.x;
    if (e < N_EDGES) {
        int d = clampi(ei[N_EDGES + e], 0, N_NODES - 1);
        atomicAdd(&g_edeg[d], 1);
    }
}

__global__ void k_scan1() {
    __shared__ int sh[1024];
    int i = blockIdx.x * 1024 + threadIdx.x;
    int v = (i < N_NODES) ? g_edeg[i] : 0;
    sh[threadIdx.x] = v;
    __syncthreads();
#pragma unroll
    for (int off = 1; off < 1024; off <<= 1) {
        int t = (threadIdx.x >= off) ? sh[threadIdx.x - off] : 0;
        __syncthreads();
        sh[threadIdx.x] += t;
        __syncthreads();
    }
    if (i < N_NODES) g_rowptr[i] = sh[threadIdx.x] - v;  // exclusive
    if (threadIdx.x == 1023) g_bsum[blockIdx.x] = sh[1023];
}

__global__ void k_scan2(int nblk) {
    __shared__ int sh[128];
    int v = (threadIdx.x < nblk) ? g_bsum[threadIdx.x] : 0;
    sh[threadIdx.x] = v;
    __syncthreads();
#pragma unroll
    for (int off = 1; off < 128; off <<= 1) {
        int t = (threadIdx.x >= off) ? sh[threadIdx.x - off] : 0;
        __syncthreads();
        sh[threadIdx.x] += t;
        __syncthreads();
    }
    if (threadIdx.x < nblk) g_boff[threadIdx.x] = sh[threadIdx.x] - v;
}

__global__ void k_scan3() {
    int i = blockIdx.x * blockDim.x + threadIdx.x;
    if (i < N_NODES) {
        int rp = g_rowptr[i] + g_boff[i >> 10];
        g_rowptr[i] = rp;
        g_cursor[i] = rp;
        g_dinv[i]   = rsqrtf((float)(g_edeg[i] + 1));   // +1 self loop, always > 0
    }
    if (i == 0) g_rowptr[N_NODES] = N_EDGES;
}

__global__ void k_scatter(const int* __restrict__ ei) {
    int e = blockIdx.x * blockDim.x + threadIdx.x;
    if (e < N_EDGES) {
        int s = clampi(ei[e], 0, N_NODES - 1);
        int d = clampi(ei[N_EDGES + e], 0, N_NODES - 1);
        int p = atomicAdd(&g_cursor[d], 1);
        if (p >= 0 && p < N_EDGES) g_col[p] = s;
    }
}

// ---------------- split-A 2xTF32 GEMM: g_h[r] = fp16( (A[r] @ W) * dinv[r] ) ----------
// A = a_big + a_small (both tf32), W single tf32. D = a_big*W + a_small*W.
// BM=128, BN=128, BK=16. 256 threads = 8 warps in 4(m) x 2(n); warp tile 32x64.
template <bool FIRST>
__global__ __launch_bounds__(256) void k_gemm_tf32(const float* __restrict__ Aext,
                                                   const float* __restrict__ W) {
    __shared__ uint32_t AsB[128][20];   // big part,   16 cols + pad
    __shared__ uint32_t AsS[128][20];   // small part
    __shared__ uint32_t Bs[16][132];    // 16 x 128 + pad

    const int m0   = blockIdx.x * 128;
    const int tid  = threadIdx.x;
    const int w    = tid >> 5, lane = tid & 31;
    const int wm   = w & 3;            // row base wm*32
    const int wn   = w >> 2;           // col base wn*64
    const int gid  = lane >> 2, tig = lane & 3;

    float acc[2][8][4] = {};

    const float4* A4 = reinterpret_cast<const float4*>(Aext);
    const float4* W4 = reinterpret_cast<const float4*>(W);

    for (int kk = 0; kk < 128; kk += 16) {
        // A tile: 128 rows x 4 quads = 512 float4, 2 per thread; split big/small
#pragma unroll
        for (int j = 0; j < 2; j++) {
            int i = tid + j * 256;
            int r = i >> 2, q = i & 3;
            int row = m0 + r;
            float4 v = make_float4(0.f, 0.f, 0.f, 0.f);
            if (row < N_NODES) {
                size_t idx = (size_t)row * NQUAD + (kk >> 2) + q;
                v = FIRST ? A4[idx] : g_buf[idx];
            }
            float vv[4] = {v.x, v.y, v.z, v.w};
#pragma unroll
            for (int u = 0; u < 4; u++) {
                uint32_t big = f2tf32(vv[u]);
                AsB[r][q * 4 + u] = big;
                AsS[r][q * 4 + u] = f2tf32(vv[u] - __uint_as_float(big));
            }
        }
        // B tile: 16 rows x 32 quads = 512 float4, 2 per thread
#pragma unroll
        for (int j = 0; j < 2; j++) {
            int i = tid + j * 256;
            int r = i >> 5, q = i & 31;
            float4 v = W4[(size_t)(kk + r) * NQUAD + q];
            Bs[r][q * 4 + 0] = f2tf32(v.x);
            Bs[r][q * 4 + 1] = f2tf32(v.y);
            Bs[r][q * 4 + 2] = f2tf32(v.z);
            Bs[r][q * 4 + 3] = f2tf32(v.w);
        }
        __syncthreads();

#pragma unroll
        for (int k8 = 0; k8 < 2; k8++) {
            const int kb = k8 * 8;
            uint32_t afb[2][4], afs[2][4];
#pragma unroll
            for (int fm = 0; fm < 2; fm++) {
                int rb = wm * 32 + fm * 16 + gid;
                afb[fm][0] = AsB[rb    ][kb + tig];
                afb[fm][1] = AsB[rb + 8][kb + tig];
                afb[fm][2] = AsB[rb    ][kb + tig + 4];
                afb[fm][3] = AsB[rb + 8][kb + tig + 4];
                afs[fm][0] = AsS[rb    ][kb + tig];
                afs[fm][1] = AsS[rb + 8][kb + tig];
                afs[fm][2] = AsS[rb    ][kb + tig + 4];
                afs[fm][3] = AsS[rb + 8][kb + tig + 4];
            }
#pragma unroll
            for (int fn = 0; fn < 8; fn++) {
                int cn = wn * 64 + fn * 8 + gid;
                uint32_t b0 = Bs[kb + tig    ][cn];
                uint32_t b1 = Bs[kb + tig + 4][cn];
                mma_tf32(acc[0][fn], afb[0], b0, b1);
                mma_tf32(acc[0][fn], afs[0], b0, b1);
                mma_tf32(acc[1][fn], afb[1], b0, b1);
                mma_tf32(acc[1][fn], afs[1], b0, b1);
            }
        }
        __syncthreads();
    }

    // epilogue: scale rows by dinv, convert to fp16, store half2 (4 B) per frag-pair
#pragma unroll
    for (int fm = 0; fm < 2; fm++) {
        int r0 = m0 + wm * 32 + fm * 16 + gid;
        int r1 = r0 + 8;
        float d0 = (r0 < N_NODES) ? g_dinv[r0] : 0.f;
        float d1 = (r1 < N_NODES) ? g_dinv[r1] : 0.f;
#pragma unroll
        for (int fn = 0; fn < 8; fn++) {
            int h2i = wn * 32 + fn * 4 + tig;    // half2 index within row (col/2)
            if (r0 < N_NODES)
                g_h[(size_t)r0 * 64 + h2i] =
                    __floats2half2_rn(acc[fm][fn][0] * d0, acc[fm][fn][1] * d0);
            if (r1 < N_NODES)
                g_h[(size_t)r1 * 64 + h2i] =
                    __floats2half2_rn(acc[fm][fn][2] * d1, acc[fm][fn][3] * d1);
        }
    }
}

// ---------------- aggregation: warp per node, fp16 rows, fp32 accumulate ----------
// out[d] = relu( dinv[d] * (g[d] + sum_{s in N(d)} g[s]) + b )
template <bool LAST>
__global__ __launch_bounds__(256) void k_agg(const float* __restrict__ bias,
                                             float* __restrict__ outExt) {
    int gw   = (blockIdx.x * blockDim.x + threadIdx.x) >> 5;
    int lane = threadIdx.x & 31;
    if (gw >= N_NODES) return;

    const uint2* H = reinterpret_cast<const uint2*>(g_h);   // 32 uint2 per row

    float4 acc;
    {
        uint2 u = H[(size_t)gw * 32 + lane];                // self-loop term
        float2 f0 = __half22float2(*reinterpret_cast<__half2*>(&u.x));
        float2 f1 = __half22float2(*reinterpret_cast<__half2*>(&u.y));
        acc = make_float4(f0.x, f0.y, f1.x, f1.y);
    }
    const int beg = g_rowptr[gw], end = g_rowptr[gw + 1];

    for (int j = beg; j < end; j += 32) {
        int jl  = j + lane;
        int idx = (jl < end) ? g_col[jl] : 0;
        int cnt = min(32, end - j);
        int t = 0;
        for (; t + 8 <= cnt; t += 8) {           // 8 independent gathers in flight
            uint2 v[8];
#pragma unroll
            for (int u = 0; u < 8; u++) {
                int s = __shfl_sync(0xffffffffu, idx, t + u);
                v[u] = H[(size_t)s * 32 + lane];
            }
#pragma unroll
            for (int u = 0; u < 8; u++) {
                float2 f0 = __half22float2(*reinterpret_cast<__half2*>(&v[u].x));
                float2 f1 = __half22float2(*reinterpret_cast<__half2*>(&v[u].y));
                acc.x += f0.x; acc.y += f0.y; acc.z += f1.x; acc.w += f1.y;
            }
        }
        for (; t < cnt; t++) {
            int s = __shfl_sync(0xffffffffu, idx, t);
            uint2 u = H[(size_t)s * 32 + lane];
            float2 f0 = __half22float2(*reinterpret_cast<__half2*>(&u.x));
            float2 f1 = __half22float2(*reinterpret_cast<__half2*>(&u.y));
            acc.x += f0.x; acc.y += f0.y; acc.z += f1.x; acc.w += f1.y;
        }
    }

    float dv  = g_dinv[gw];
    float4 bb = reinterpret_cast<const float4*>(bias)[lane];
    float4 o;
    o.x = fmaxf(acc.x * dv + bb.x, 0.f);
    o.y = fmaxf(acc.y * dv + bb.y, 0.f);
    o.z = fmaxf(acc.z * dv + bb.z, 0.f);
    o.w = fmaxf(acc.w * dv + bb.w, 0.f);
    if (LAST) {
        reinterpret_cast<float4*>(outExt)[(size_t)gw * NQUAD + lane] = o;
    } else {
        g_buf[(size_t)gw * NQUAD + lane] = o;
    }
}

// ---------------- launch ----------------
extern "C" void kernel_launch(void* const* d_in, const int* in_sizes, int n_in,
                              void* d_out, int out_size) {
    const float* x  = (const float*)d_in[0];
    const int*   ei = (const int*)d_in[1];          // int32 edge_index
    const float* W0 = (const float*)d_in[2];
    const float* b0 = (const float*)d_in[3];
    const float* W1 = (const float*)d_in[4];
    const float* b1 = (const float*)d_in[5];
    const float* W2 = (const float*)d_in[6];
    const float* b2 = (const float*)d_in[7];
    float* out = (float*)d_out;

    const int nodeBlocks = (N_NODES + 255) / 256;
    const int edgeBlocks = (N_EDGES + 255) / 256;
    const int scanBlocks = (N_NODES + 1023) / 1024;   // 98
    const int gemmBlocks = (N_NODES + 127) / 128;     // 782
    const int aggBlocks  = (N_NODES * 32 + 255) / 256;

    // CSR build (recomputed every call: deterministic work)
    k_zero_deg<<<nodeBlocks, 256>>>();
    k_hist<<<edgeBlocks, 256>>>(ei);
    k_scan1<<<scanBlocks, 1024>>>();
    k_scan2<<<1, 128>>>(scanBlocks);
    k_scan3<<<nodeBlocks, 256>>>();
    k_scatter<<<edgeBlocks, 256>>>(ei);

    // layer 0
    k_gemm_tf32<true ><<<gemmBlocks, 256>>>(x, W0);
    k_agg      <false><<<aggBlocks, 256>>>(b0, nullptr);
    // layer 1
    k_gemm_tf32<false><<<gemmBlocks, 256>>>(nullptr, W1);
    k_agg      <false><<<aggBlocks, 256>>>(b1, nullptr);
    // layer 2
    k_gemm_tf32<false><<<gemmBlocks, 256>>>(nullptr, W2);
    k_agg      <true ><<<aggBlocks, 256>>>(b2, out);
}

// round 6
// speedup vs baseline: 1.4589x; 1.1439x over previous
#include <cuda_runtime.h>
#include <cuda_fp16.h>
#include <cuda_bf16.h>
#include <cstddef>
#include <cstdint>

#define N_NODES 100000
#define N_EDGES 3200000
#define NQUAD   32          // 128 floats = 32 float4 per node row

// ---------------- scratch (static __device__, allowed) ----------------
__device__ int     g_edeg[N_NODES];
__device__ float   g_dinv[N_NODES];
__device__ int     g_rowptr[N_NODES + 1];
__device__ int     g_cursor[N_NODES];
__device__ int     g_col[N_EDGES];
__device__ __half2 g_h  [(size_t)N_NODES * 64];     // fp16 scaled GEMM output (256 B/row)
__device__ float4  g_buf[(size_t)N_NODES * NQUAD];  // inter-layer activations (fp32)
__device__ int     g_bsum[128];
__device__ int     g_boff[128];

static __device__ __forceinline__ int clampi(int v, int lo, int hi) {
    return v < lo ? lo : (v > hi ? hi : v);
}

// fp16 MMA m16n8k16, fp32 accumulate
static __device__ __forceinline__ void mma_f16(float* c, const uint32_t* a,
                                               uint32_t b0, uint32_t b1) {
    asm volatile(
        "mma.sync.aligned.m16n8k16.row.col.f32.f16.f16.f32 "
        "{%0,%1,%2,%3}, {%4,%5,%6,%7}, {%8,%9}, {%0,%1,%2,%3};\n"
        : "+f"(c[0]), "+f"(c[1]), "+f"(c[2]), "+f"(c[3])
        : "r"(a[0]), "r"(a[1]), "r"(a[2]), "r"(a[3]), "r"(b0), "r"(b1));
}

// ---------------- preprocessing: degree / CSR ----------------
__global__ void k_zero_deg() {
    int i = blockIdx.x * blockDim.x + threadIdx.x;
    if (i < N_NODES) g_edeg[i] = 0;
}

__global__ void k_hist(const int* __restrict__ ei) {
    int e = blockIdx.x * blockDim.x + threadIdx.x;
    if (e < N_EDGES) {
        int d = clampi(ei[N_EDGES + e], 0, N_NODES - 1);
        atomicAdd(&g_edeg[d], 1);
    }
}

__global__ void k_scan1() {
    __shared__ int sh[1024];
    int i = blockIdx.x * 1024 + threadIdx.x;
    int v = (i < N_NODES) ? g_edeg[i] : 0;
    sh[threadIdx.x] = v;
    __syncthreads();
#pragma unroll
    for (int off = 1; off < 1024; off <<= 1) {
        int t = (threadIdx.x >= off) ? sh[threadIdx.x - off] : 0;
        __syncthreads();
        sh[threadIdx.x] += t;
        __syncthreads();
    }
    if (i < N_NODES) g_rowptr[i] = sh[threadIdx.x] - v;  // exclusive
    if (threadIdx.x == 1023) g_bsum[blockIdx.x] = sh[1023];
}

__global__ void k_scan2(int nblk) {
    __shared__ int sh[128];
    int v = (threadIdx.x < nblk) ? g_bsum[threadIdx.x] : 0;
    sh[threadIdx.x] = v;
    __syncthreads();
#pragma unroll
    for (int off = 1; off < 128; off <<= 1) {
        int t = (threadIdx.x >= off) ? sh[threadIdx.x - off] : 0;
        __syncthreads();
        sh[threadIdx.x] += t;
        __syncthreads();
    }
    if (threadIdx.x < nblk) g_boff[threadIdx.x] = sh[threadIdx.x] - v;
}

__global__ void k_scan3() {
    int i = blockIdx.x * blockDim.x + threadIdx.x;
    if (i < N_NODES) {
        int rp = g_rowptr[i] + g_boff[i >> 10];
        g_rowptr[i] = rp;
        g_cursor[i] = rp;
        g_dinv[i]   = rsqrtf((float)(g_edeg[i] + 1));   // +1 self loop, always > 0
    }
    if (i == 0) g_rowptr[N_NODES] = N_EDGES;
}

__global__ void k_scatter(const int* __restrict__ ei) {
    int e = blockIdx.x * blockDim.x + threadIdx.x;
    if (e < N_EDGES) {
        int s = clampi(ei[e], 0, N_NODES - 1);
        int d = clampi(ei[N_EDGES + e], 0, N_NODES - 1);
        int p = atomicAdd(&g_cursor[d], 1);
        if (p >= 0 && p < N_EDGES) g_col[p] = s;
    }
}

// ---------------- fp16 tensor-core GEMM: g_h[r] = fp16( (A[r] @ W) * dinv[r] ) --------
// mma.sync.m16n8k16 f16 (fp32 accum). BM=128, BN=128, BK=64.
// 256 threads = 8 warps in 4(m) x 2(n); warp tile 32x64: 2 m-frags x 8 n-frags.
template <bool FIRST>
__global__ __launch_bounds__(256) void k_gemm_f16(const float* __restrict__ Aext,
                                                  const float* __restrict__ W) {
    __shared__ __half2 As [128][33];   // 128 rows x 64 halfs (32 half2) + pad
    __shared__ __half  BsT[128][66];   // 128 n-cols x 64 k-halfs + pad (transposed W)

    const int m0   = blockIdx.x * 128;
    const int tid  = threadIdx.x;
    const int w    = tid >> 5, lane = tid & 31;
    const int wm   = w & 3;            // row base wm*32
    const int wn   = w >> 2;           // col base wn*64
    const int gid  = lane >> 2, tig = lane & 3;

    float acc[2][8][4] = {};

    const float4* A4 = reinterpret_cast<const float4*>(Aext);
    const float4* W4 = reinterpret_cast<const float4*>(W);

    for (int kk = 0; kk < 128; kk += 64) {
        // A chunk: 128 rows x 16 quads = 2048 float4, 8 per thread
#pragma unroll
        for (int j = 0; j < 8; j++) {
            int i = tid + j * 256;
            int r = i >> 4, q = i & 15;
            int row = m0 + r;
            float4 v = make_float4(0.f, 0.f, 0.f, 0.f);
            if (row < N_NODES) {
                size_t idx = (size_t)row * NQUAD + (kk >> 2) + q;
                v = FIRST ? A4[idx] : g_buf[idx];
            }
            As[r][q * 2    ] = __floats2half2_rn(v.x, v.y);
            As[r][q * 2 + 1] = __floats2half2_rn(v.z, v.w);
        }
        // B chunk: 64 k-rows x 32 quads = 2048 float4, 8 per thread; store transposed
#pragma unroll
        for (int j = 0; j < 8; j++) {
            int i = tid + j * 256;
            int r = i >> 5, q = i & 31;          // k row r (0..63), n quad q
            float4 v = W4[(size_t)(kk + r) * NQUAD + q];
            BsT[q * 4 + 0][r] = __float2half(v.x);
            BsT[q * 4 + 1][r] = __float2half(v.y);
            BsT[q * 4 + 2][r] = __float2half(v.z);
            BsT[q * 4 + 3][r] = __float2half(v.w);
        }
        __syncthreads();

#pragma unroll
        for (int c = 0; c < 4; c++) {            // four k16 chunks in this BK=64 tile
            const int h2 = c * 8;                // half2 base index for this chunk
            uint32_t af[2][4];
#pragma unroll
            for (int fm = 0; fm < 2; fm++) {
                int rb = wm * 32 + fm * 16 + gid;
                af[fm][0] = *reinterpret_cast<const uint32_t*>(&As[rb    ][h2 + tig]);
                af[fm][1] = *reinterpret_cast<const uint32_t*>(&As[rb + 8][h2 + tig]);
                af[fm][2] = *reinterpret_cast<const uint32_t*>(&As[rb    ][h2 + tig + 4]);
                af[fm][3] = *reinterpret_cast<const uint32_t*>(&As[rb + 8][h2 + tig + 4]);
            }
#pragma unroll
            for (int fn = 0; fn < 8; fn++) {
                int cn = wn * 64 + fn * 8 + gid;
                const __half2* brow = reinterpret_cast<const __half2*>(&BsT[cn][0]);
                uint32_t b0 = *reinterpret_cast<const uint32_t*>(&brow[h2 + tig]);
                uint32_t b1 = *reinterpret_cast<const uint32_t*>(&brow[h2 + tig + 4]);
                mma_f16(acc[0][fn], af[0], b0, b1);
                mma_f16(acc[1][fn], af[1], b0, b1);
            }
        }
        __syncthreads();
    }

    // epilogue: scale rows by dinv, convert to fp16, store half2
#pragma unroll
    for (int fm = 0; fm < 2; fm++) {
        int r0 = m0 + wm * 32 + fm * 16 + gid;
        int r1 = r0 + 8;
        float d0 = (r0 < N_NODES) ? g_dinv[r0] : 0.f;
        float d1 = (r1 < N_NODES) ? g_dinv[r1] : 0.f;
#pragma unroll
        for (int fn = 0; fn < 8; fn++) {
            int h2i = wn * 32 + fn * 4 + tig;    // half2 index within row
            if (r0 < N_NODES)
                g_h[(size_t)r0 * 64 + h2i] =
                    __floats2half2_rn(acc[fm][fn][0] * d0, acc[fm][fn][1] * d0);
            if (r1 < N_NODES)
                g_h[(size_t)r1 * 64 + h2i] =
                    __floats2half2_rn(acc[fm][fn][2] * d1, acc[fm][fn][3] * d1);
        }
    }
}

// ---------------- aggregation: warp per node, fp16 rows, fp32 accumulate ----------
// out[d] = relu( dinv[d] * (g[d] + sum_{s in N(d)} g[s]) + b )
template <bool LAST>
__global__ __launch_bounds__(256) void k_agg(const float* __restrict__ bias,
                                             float* __restrict__ outExt) {
    int gw   = (blockIdx.x * blockDim.x + threadIdx.x) >> 5;
    int lane = threadIdx.x & 31;
    if (gw >= N_NODES) return;

    const uint2* H = reinterpret_cast<const uint2*>(g_h);   // 32 uint2 per row

    float4 acc;
    {
        uint2 u = H[(size_t)gw * 32 + lane];                // self-loop term
        float2 f0 = __half22float2(*reinterpret_cast<__half2*>(&u.x));
        float2 f1 = __half22float2(*reinterpret_cast<__half2*>(&u.y));
        acc = make_float4(f0.x, f0.y, f1.x, f1.y);
    }
    const int beg = g_rowptr[gw], end = g_rowptr[gw + 1];

    for (int j = beg; j < end; j += 32) {
        int jl  = j + lane;
        int idx = (jl < end) ? g_col[jl] : 0;
        int cnt = min(32, end - j);
        int t = 0;
        for (; t + 8 <= cnt; t += 8) {           // 8 independent gathers in flight
            uint2 v[8];
#pragma unroll
            for (int u = 0; u < 8; u++) {
                int s = __shfl_sync(0xffffffffu, idx, t + u);
                v[u] = H[(size_t)s * 32 + lane];
            }
#pragma unroll
            for (int u = 0; u < 8; u++) {
                float2 f0 = __half22float2(*reinterpret_cast<__half2*>(&v[u].x));
                float2 f1 = __half22float2(*reinterpret_cast<__half2*>(&v[u].y));
                acc.x += f0.x; acc.y += f0.y; acc.z += f1.x; acc.w += f1.y;
            }
        }
        for (; t < cnt; t++) {
            int s = __shfl_sync(0xffffffffu, idx, t);
            uint2 u = H[(size_t)s * 32 + lane];
            float2 f0 = __half22float2(*reinterpret_cast<__half2*>(&u.x));
            float2 f1 = __half22float2(*reinterpret_cast<__half2*>(&u.y));
            acc.x += f0.x; acc.y += f0.y; acc.z += f1.x; acc.w += f1.y;
        }
    }

    float dv  = g_dinv[gw];
    float4 bb = reinterpret_cast<const float4*>(bias)[lane];
    float4 o;
    o.x = fmaxf(acc.x * dv + bb.x, 0.f);
    o.y = fmaxf(acc.y * dv + bb.y, 0.f);
    o.z = fmaxf(acc.z * dv + bb.z, 0.f);
    o.w = fmaxf(acc.w * dv + bb.w, 0.f);
    if (LAST) {
        reinterpret_cast<float4*>(outExt)[(size_t)gw * NQUAD + lane] = o;
    } else {
        g_buf[(size_t)gw * NQUAD + lane] = o;
    }
}

// ---------------- launch ----------------
extern "C" void kernel_launch(void* const* d_in, const int* in_sizes, int n_in,
                              void* d_out, int out_size) {
    const float* x  = (const float*)d_in[0];
    const int*   ei = (const int*)d_in[1];          // int32 edge_index
    const float* W0 = (const float*)d_in[2];
    const float* b0 = (const float*)d_in[3];
    const float* W1 = (const float*)d_in[4];
    const float* b1 = (const float*)d_in[5];
    const float* W2 = (const float*)d_in[6];
    const float* b2 = (const float*)d_in[7];
    float* out = (float*)d_out;

    const int nodeBlocks = (N_NODES + 255) / 256;
    const int edgeBlocks = (N_EDGES + 255) / 256;
    const int scanBlocks = (N_NODES + 1023) / 1024;   // 98
    const int gemmBlocks = (N_NODES + 127) / 128;     // 782
    const int aggBlocks  = (N_NODES * 32 + 255) / 256;

    // CSR build (recomputed every call: deterministic work)
    k_zero_deg<<<nodeBlocks, 256>>>();
    k_hist<<<edgeBlocks, 256>>>(ei);
    k_scan1<<<scanBlocks, 1024>>>();
    k_scan2<<<1, 128>>>(scanBlocks);
    k_scan3<<<nodeBlocks, 256>>>();
    k_scatter<<<edgeBlocks, 256>>>(ei);

    // layer 0
    k_gemm_f16<true ><<<gemmBlocks, 256>>>(x, W0);
    k_agg     <false><<<aggBlocks, 256>>>(b0, nullptr);
    // layer 1
    k_gemm_f16<false><<<gemmBlocks, 256>>>(nullptr, W1);
    k_agg     <false><<<aggBlocks, 256>>>(b1, nullptr);
    // layer 2
    k_gemm_f16<false><<<gemmBlocks, 256>>>(nullptr, W2);
    k_agg     <true ><<<aggBlocks, 256>>>(b2, out);
}

// round 7
// speedup vs baseline: 1.5776x; 1.0813x over previous
#include <cuda_runtime.h>
#include <cuda_fp16.h>
#include <cuda_bf16.h>
#include <cstddef>
#include <cstdint>

#define N_NODES 100000
#define N_EDGES 3200000
#define NQUAD   32          // 128 floats = 32 float4 per node row

// ---------------- scratch (static __device__, allowed) ----------------
__device__ int     g_edeg[N_NODES];
__device__ float   g_dinv[N_NODES];
__device__ int     g_rowptr[N_NODES + 1];
__device__ int     g_cursor[N_NODES];
__device__ int     g_col[N_EDGES];
__device__ __half2 g_h  [(size_t)N_NODES * 64];     // fp16 scaled GEMM output (256 B/row)
__device__ float4  g_buf[(size_t)N_NODES * NQUAD];  // inter-layer activations (fp32)
__device__ int     g_bsum[128];
__device__ int     g_boff[128];

static __device__ __forceinline__ int clampi(int v, int lo, int hi) {
    return v < lo ? lo : (v > hi ? hi : v);
}

// fp16 MMA m16n8k16, fp32 accumulate
static __device__ __forceinline__ void mma_f16(float* c, const uint32_t* a,
                                               uint32_t b0, uint32_t b1) {
    asm volatile(
        "mma.sync.aligned.m16n8k16.row.col.f32.f16.f16.f32 "
        "{%0,%1,%2,%3}, {%4,%5,%6,%7}, {%8,%9}, {%0,%1,%2,%3};\n"
        : "+f"(c[0]), "+f"(c[1]), "+f"(c[2]), "+f"(c[3])
        : "r"(a[0]), "r"(a[1]), "r"(a[2]), "r"(a[3]), "r"(b0), "r"(b1));
}

// ---------------- preprocessing: degree / CSR ----------------
__global__ void k_zero_deg() {
    int i = blockIdx.x * blockDim.x + threadIdx.x;
    if (i < N_NODES) g_edeg[i] = 0;
}

__global__ void k_hist(const int* __restrict__ ei) {
    int e = blockIdx.x * blockDim.x + threadIdx.x;
    if (e < N_EDGES) {
        int d = clampi(ei[N_EDGES + e], 0, N_NODES - 1);
        atomicAdd(&g_edeg[d], 1);
    }
}

__global__ void k_scan1() {
    __shared__ int sh[1024];
    int i = blockIdx.x * 1024 + threadIdx.x;
    int v = (i < N_NODES) ? g_edeg[i] : 0;
    sh[threadIdx.x] = v;
    __syncthreads();
#pragma unroll
    for (int off = 1; off < 1024; off <<= 1) {
        int t = (threadIdx.x >= off) ? sh[threadIdx.x - off] : 0;
        __syncthreads();
        sh[threadIdx.x] += t;
        __syncthreads();
    }
    if (i < N_NODES) g_rowptr[i] = sh[threadIdx.x] - v;  // exclusive
    if (threadIdx.x == 1023) g_bsum[blockIdx.x] = sh[1023];
}

__global__ void k_scan2(int nblk) {
    __shared__ int sh[128];
    int v = (threadIdx.x < nblk) ? g_bsum[threadIdx.x] : 0;
    sh[threadIdx.x] = v;
    __syncthreads();
#pragma unroll
    for (int off = 1; off < 128; off <<= 1) {
        int t = (threadIdx.x >= off) ? sh[threadIdx.x - off] : 0;
        __syncthreads();
        sh[threadIdx.x] += t;
        __syncthreads();
    }
    if (threadIdx.x < nblk) g_boff[threadIdx.x] = sh[threadIdx.x] - v;
}

__global__ void k_scan3() {
    int i = blockIdx.x * blockDim.x + threadIdx.x;
    if (i < N_NODES) {
        int rp = g_rowptr[i] + g_boff[i >> 10];
        g_rowptr[i] = rp;
        g_cursor[i] = rp;
        g_dinv[i]   = rsqrtf((float)(g_edeg[i] + 1));   // +1 self loop, always > 0
    }
    if (i == 0) g_rowptr[N_NODES] = N_EDGES;
}

__global__ void k_scatter(const int* __restrict__ ei) {
    int e = blockIdx.x * blockDim.x + threadIdx.x;
    if (e < N_EDGES) {
        int s = clampi(ei[e], 0, N_NODES - 1);
        int d = clampi(ei[N_EDGES + e], 0, N_NODES - 1);
        int p = atomicAdd(&g_cursor[d], 1);
        if (p >= 0 && p < N_EDGES) g_col[p] = s;
    }
}

// ---------------- fp16 tensor-core GEMM: g_h[r] = fp16( (A[r] @ W) * dinv[r] ) --------
// mma.sync.m16n8k16 f16 (fp32 accum). BM=128, BN=128, BK=64.
// B stored k-pair-major: Bs[kpair][n] as half2(k, k+1) -> one LDS.32 per b-frag reg,
// filled with aligned 16B stores. Pads (36 / 136 words) make every smem access phase
// hit 32 distinct banks.
template <bool FIRST>
__global__ __launch_bounds__(256) void k_gemm_f16(const float* __restrict__ Aext,
                                                  const float* __restrict__ W) {
    __shared__ __half2 As[128][36];    // [row][k half2], 32 data + 4 pad
    __shared__ __half2 Bs[32][136];    // [kpair][n], 128 data + 8 pad

    const int m0   = blockIdx.x * 128;
    const int tid  = threadIdx.x;
    const int w    = tid >> 5, lane = tid & 31;
    const int wm   = w & 3;            // row base wm*32
    const int wn   = w >> 2;           // col base wn*64
    const int gid  = lane >> 2, tig = lane & 3;

    float acc[2][8][4] = {};

    const float4* A4 = reinterpret_cast<const float4*>(Aext);
    const float4* W4 = reinterpret_cast<const float4*>(W);

    for (int kk = 0; kk < 128; kk += 64) {
        // A chunk: 128 rows x 16 quads = 2048 float4, 8 per thread
#pragma unroll
        for (int j = 0; j < 8; j++) {
            int i = tid + j * 256;
            int r = i >> 4, q = i & 15;
            int row = m0 + r;
            float4 v = make_float4(0.f, 0.f, 0.f, 0.f);
            if (row < N_NODES) {
                size_t idx = (size_t)row * NQUAD + (kk >> 2) + q;
                v = FIRST ? A4[idx] : g_buf[idx];
            }
            As[r][q * 2    ] = __floats2half2_rn(v.x, v.y);
            As[r][q * 2 + 1] = __floats2half2_rn(v.z, v.w);
        }
        // B chunk: 32 kpairs x 32 quads = 1024 (r,q) pairs, 4 per thread.
        // Each thread loads k rows (2r, 2r+1) at n-quad q and stores 4 half2 = 16B.
#pragma unroll
        for (int j = 0; j < 4; j++) {
            int i = tid + j * 256;
            int r = i >> 5, q = i & 31;
            float4 v0 = W4[(size_t)(kk + 2 * r    ) * NQUAD + q];
            float4 v1 = W4[(size_t)(kk + 2 * r + 1) * NQUAD + q];
            __half2 p0 = __floats2half2_rn(v0.x, v1.x);
            __half2 p1 = __floats2half2_rn(v0.y, v1.y);
            __half2 p2 = __floats2half2_rn(v0.z, v1.z);
            __half2 p3 = __floats2half2_rn(v0.w, v1.w);
            uint4 pk;
            pk.x = *reinterpret_cast<uint32_t*>(&p0);
            pk.y = *reinterpret_cast<uint32_t*>(&p1);
            pk.z = *reinterpret_cast<uint32_t*>(&p2);
            pk.w = *reinterpret_cast<uint32_t*>(&p3);
            *reinterpret_cast<uint4*>(&Bs[r][q * 4]) = pk;
        }
        __syncthreads();

#pragma unroll
        for (int c = 0; c < 4; c++) {            // four k16 chunks in this BK=64 tile
            const int h2 = c * 8;                // half2 base (A) / kpair base (B)
            uint32_t af[2][4];
#pragma unroll
            for (int fm = 0; fm < 2; fm++) {
                int rb = wm * 32 + fm * 16 + gid;
                af[fm][0] = *reinterpret_cast<const uint32_t*>(&As[rb    ][h2 + tig]);
                af[fm][1] = *reinterpret_cast<const uint32_t*>(&As[rb + 8][h2 + tig]);
                af[fm][2] = *reinterpret_cast<const uint32_t*>(&As[rb    ][h2 + tig + 4]);
                af[fm][3] = *reinterpret_cast<const uint32_t*>(&As[rb + 8][h2 + tig + 4]);
            }
#pragma unroll
            for (int fn = 0; fn < 8; fn++) {
                int cn = wn * 64 + fn * 8 + gid;
                uint32_t b0 = *reinterpret_cast<const uint32_t*>(&Bs[h2 + tig    ][cn]);
                uint32_t b1 = *reinterpret_cast<const uint32_t*>(&Bs[h2 + tig + 4][cn]);
                mma_f16(acc[0][fn], af[0], b0, b1);
                mma_f16(acc[1][fn], af[1], b0, b1);
            }
        }
        __syncthreads();
    }

    // epilogue: scale rows by dinv, convert to fp16, store half2
#pragma unroll
    for (int fm = 0; fm < 2; fm++) {
        int r0 = m0 + wm * 32 + fm * 16 + gid;
        int r1 = r0 + 8;
        float d0 = (r0 < N_NODES) ? g_dinv[r0] : 0.f;
        float d1 = (r1 < N_NODES) ? g_dinv[r1] : 0.f;
#pragma unroll
        for (int fn = 0; fn < 8; fn++) {
            int h2i = wn * 32 + fn * 4 + tig;    // half2 index within row
            if (r0 < N_NODES)
                g_h[(size_t)r0 * 64 + h2i] =
                    __floats2half2_rn(acc[fm][fn][0] * d0, acc[fm][fn][1] * d0);
            if (r1 < N_NODES)
                g_h[(size_t)r1 * 64 + h2i] =
                    __floats2half2_rn(acc[fm][fn][2] * d1, acc[fm][fn][3] * d1);
        }
    }
}

// ---------------- aggregation: warp per node, fp16 rows, fp32 accumulate ----------
// out[d] = relu( dinv[d] * (g[d] + sum_{s in N(d)} g[s]) + b )
template <bool LAST>
__global__ __launch_bounds__(256) void k_agg(const float* __restrict__ bias,
                                             float* __restrict__ outExt) {
    int gw   = (blockIdx.x * blockDim.x + threadIdx.x) >> 5;
    int lane = threadIdx.x & 31;
    if (gw >= N_NODES) return;

    const uint2* H = reinterpret_cast<const uint2*>(g_h);   // 32 uint2 per row

    float4 acc;
    {
        uint2 u = H[(size_t)gw * 32 + lane];                // self-loop term
        float2 f0 = __half22float2(*reinterpret_cast<__half2*>(&u.x));
        float2 f1 = __half22float2(*reinterpret_cast<__half2*>(&u.y));
        acc = make_float4(f0.x, f0.y, f1.x, f1.y);
    }
    const int beg = g_rowptr[gw], end = g_rowptr[gw + 1];

    for (int j = beg; j < end; j += 32) {
        int jl  = j + lane;
        int idx = (jl < end) ? g_col[jl] : 0;
        int cnt = min(32, end - j);
        int t = 0;
        for (; t + 8 <= cnt; t += 8) {           // 8 independent gathers in flight
            uint2 v[8];
#pragma unroll
            for (int u = 0; u < 8; u++) {
                int s = __shfl_sync(0xffffffffu, idx, t + u);
                v[u] = H[(size_t)s * 32 + lane];
            }
#pragma unroll
            for (int u = 0; u < 8; u++) {
                float2 f0 = __half22float2(*reinterpret_cast<__half2*>(&v[u].x));
                float2 f1 = __half22float2(*reinterpret_cast<__half2*>(&v[u].y));
                acc.x += f0.x; acc.y += f0.y; acc.z += f1.x; acc.w += f1.y;
            }
        }
        for (; t < cnt; t++) {
            int s = __shfl_sync(0xffffffffu, idx, t);
            uint2 u = H[(size_t)s * 32 + lane];
            float2 f0 = __half22float2(*reinterpret_cast<__half2*>(&u.x));
            float2 f1 = __half22float2(*reinterpret_cast<__half2*>(&u.y));
            acc.x += f0.x; acc.y += f0.y; acc.z += f1.x; acc.w += f1.y;
        }
    }

    float dv  = g_dinv[gw];
    float4 bb = reinterpret_cast<const float4*>(bias)[lane];
    float4 o;
    o.x = fmaxf(acc.x * dv + bb.x, 0.f);
    o.y = fmaxf(acc.y * dv + bb.y, 0.f);
    o.z = fmaxf(acc.z * dv + bb.z, 0.f);
    o.w = fmaxf(acc.w * dv + bb.w, 0.f);
    if (LAST) {
        reinterpret_cast<float4*>(outExt)[(size_t)gw * NQUAD + lane] = o;
    } else {
        g_buf[(size_t)gw * NQUAD + lane] = o;
    }
}

// ---------------- launch ----------------
extern "C" void kernel_launch(void* const* d_in, const int* in_sizes, int n_in,
                              void* d_out, int out_size) {
    const float* x  = (const float*)d_in[0];
    const int*   ei = (const int*)d_in[1];          // int32 edge_index
    const float* W0 = (const float*)d_in[2];
    const float* b0 = (const float*)d_in[3];
    const float* W1 = (const float*)d_in[4];
    const float* b1 = (const float*)d_in[5];
    const float* W2 = (const float*)d_in[6];
    const float* b2 = (const float*)d_in[7];
    float* out = (float*)d_out;

    const int nodeBlocks = (N_NODES + 255) / 256;
    const int edgeBlocks = (N_EDGES + 255) / 256;
    const int scanBlocks = (N_NODES + 1023) / 1024;   // 98
    const int gemmBlocks = (N_NODES + 127) / 128;     // 782
    const int aggBlocks  = (N_NODES * 32 + 255) / 256;

    // CSR build (recomputed every call: deterministic work)
    k_zero_deg<<<nodeBlocks, 256>>>();
    k_hist<<<edgeBlocks, 256>>>(ei);
    k_scan1<<<scanBlocks, 1024>>>();
    k_scan2<<<1, 128>>>(scanBlocks);
    k_scan3<<<nodeBlocks, 256>>>();
    k_scatter<<<edgeBlocks, 256>>>(ei);

    // layer 0
    k_gemm_f16<true ><<<gemmBlocks, 256>>>(x, W0);
    k_agg     <false><<<aggBlocks, 256>>>(b0, nullptr);
    // layer 1
    k_gemm_f16<false><<<gemmBlocks, 256>>>(nullptr, W1);
    k_agg     <false><<<aggBlocks, 256>>>(b1, nullptr);
    // layer 2
    k_gemm_f16<false><<<gemmBlocks, 256>>>(nullptr, W2);
    k_agg     <true ><<<aggBlocks, 256>>>(b2, out);
}

// round 8
// speedup vs baseline: 1.6557x; 1.0495x over previous
#include <cuda_runtime.h>
#include <cuda_fp16.h>
#include <cuda_bf16.h>
#include <cstddef>
#include <cstdint>

#define N_NODES 100000
#define N_EDGES 3200000
#define NQUAD   32          // 128 floats = 32 float4 per node row
#define NTILES  782         // ceil(N_NODES / 128)
#define GEMM_GRID 148

// ---------------- scratch (static __device__, allowed) ----------------
__device__ int     g_edeg[N_NODES];
__device__ float   g_dinv[N_NODES];
__device__ int     g_rowptr[N_NODES + 1];
__device__ int     g_cursor[N_NODES];
__device__ int     g_col[N_EDGES];
__device__ __half2 g_h  [(size_t)N_NODES * 64];     // fp16 scaled GEMM output (256 B/row)
__device__ float4  g_buf[(size_t)N_NODES * NQUAD];  // inter-layer activations (fp32)
__device__ int     g_bsum[128];
__device__ int     g_boff[128];

static __device__ __forceinline__ int clampi(int v, int lo, int hi) {
    return v < lo ? lo : (v > hi ? hi : v);
}

static __device__ __forceinline__ uint32_t h2u(__half2 h) {
    return *reinterpret_cast<uint32_t*>(&h);
}

// fp16 MMA m16n8k16, fp32 accumulate
static __device__ __forceinline__ void mma_f16(float* c, const uint32_t* a,
                                               uint32_t b0, uint32_t b1) {
    asm volatile(
        "mma.sync.aligned.m16n8k16.row.col.f32.f16.f16.f32 "
        "{%0,%1,%2,%3}, {%4,%5,%6,%7}, {%8,%9}, {%0,%1,%2,%3};\n"
        : "+f"(c[0]), "+f"(c[1]), "+f"(c[2]), "+f"(c[3])
        : "r"(a[0]), "r"(a[1]), "r"(a[2]), "r"(a[3]), "r"(b0), "r"(b1));
}

// ---------------- preprocessing: degree / CSR ----------------
__global__ void k_zero_deg() {
    int i = blockIdx.x * blockDim.x + threadIdx.x;
    if (i < N_NODES) g_edeg[i] = 0;
}

__global__ void k_hist(const int* __restrict__ ei) {
    int e = blockIdx.x * blockDim.x + threadIdx.x;
    if (e < N_EDGES) {
        int d = clampi(ei[N_EDGES + e], 0, N_NODES - 1);
        atomicAdd(&g_edeg[d], 1);
    }
}

__global__ void k_scan1() {
    __shared__ int sh[1024];
    int i = blockIdx.x * 1024 + threadIdx.x;
    int v = (i < N_NODES) ? g_edeg[i] : 0;
    sh[threadIdx.x] = v;
    __syncthreads();
#pragma unroll
    for (int off = 1; off < 1024; off <<= 1) {
        int t = (threadIdx.x >= off) ? sh[threadIdx.x - off] : 0;
        __syncthreads();
        sh[threadIdx.x] += t;
        __syncthreads();
    }
    if (i < N_NODES) g_rowptr[i] = sh[threadIdx.x] - v;  // exclusive
    if (threadIdx.x == 1023) g_bsum[blockIdx.x] = sh[1023];
}

__global__ void k_scan2(int nblk) {
    __shared__ int sh[128];
    int v = (threadIdx.x < nblk) ? g_bsum[threadIdx.x] : 0;
    sh[threadIdx.x] = v;
    __syncthreads();
#pragma unroll
    for (int off = 1; off < 128; off <<= 1) {
        int t = (threadIdx.x >= off) ? sh[threadIdx.x - off] : 0;
        __syncthreads();
        sh[threadIdx.x] += t;
        __syncthreads();
    }
    if (threadIdx.x < nblk) g_boff[threadIdx.x] = sh[threadIdx.x] - v;
}

__global__ void k_scan3() {
    int i = blockIdx.x * blockDim.x + threadIdx.x;
    if (i < N_NODES) {
        int rp = g_rowptr[i] + g_boff[i >> 10];
        g_rowptr[i] = rp;
        g_cursor[i] = rp;
        g_dinv[i]   = rsqrtf((float)(g_edeg[i] + 1));   // +1 self loop, always > 0
    }
    if (i == 0) g_rowptr[N_NODES] = N_EDGES;
}

__global__ void k_scatter(const int* __restrict__ ei) {
    int e = blockIdx.x * blockDim.x + threadIdx.x;
    if (e < N_EDGES) {
        int s = clampi(ei[e], 0, N_NODES - 1);
        int d = clampi(ei[N_EDGES + e], 0, N_NODES - 1);
        int p = atomicAdd(&g_cursor[d], 1);
        if (p >= 0 && p < N_EDGES) g_col[p] = s;
    }
}

// ---------------- persistent fp16 GEMM: g_h[r] = fp16( (A[r] @ W) * dinv[r] ) --------
// 148 blocks x 512 threads. W resident in smem (fp16, k-pair-major, full K=128).
// Each block loops over M-tiles (stride gridDim); A double-buffered: next tile's
// global loads (converted to half2 in regs) overlap current tile's MMAs.
// One __syncthreads per tile. Dynamic smem: 2 A bufs (128x68 half2) + B (64x136 half2).
#define AS_STRIDE 68
#define AS_ELEMS  (128 * AS_STRIDE)          // per buffer, in half2
#define BS_STRIDE 136
#define SMEM_GEMM ((2 * AS_ELEMS + 64 * BS_STRIDE) * 4)   // 104448 bytes

template <bool FIRST>
__global__ __launch_bounds__(512) void k_gemm_f16(const float* __restrict__ Aext,
                                                  const float* __restrict__ W) {
    extern __shared__ __align__(16) char smem_raw[];
    __half2* sA = reinterpret_cast<__half2*>(smem_raw);              // 2 x [128][68]
    __half2* sB = reinterpret_cast<__half2*>(smem_raw + 2 * AS_ELEMS * 4); // [64][136]

    const int tid  = threadIdx.x;
    const int w    = tid >> 5, lane = tid & 31;
    const int wm   = w & 3;            // row base wm*32
    const int wn   = w >> 2;           // col base wn*32
    const int gid  = lane >> 2, tig = lane & 3;

    const float4* A4 = reinterpret_cast<const float4*>(Aext);
    const float4* W4 = reinterpret_cast<const float4*>(W);

    // ---- load W once: 64 kpairs x 32 quads = 2048 items, 4 per thread ----
#pragma unroll
    for (int j = 0; j < 4; j++) {
        int i = tid + j * 512;
        int r = i >> 5, q = i & 31;
        float4 v0 = W4[(size_t)(2 * r    ) * NQUAD + q];
        float4 v1 = W4[(size_t)(2 * r + 1) * NQUAD + q];
        uint4 pk;
        pk.x = h2u(__floats2half2_rn(v0.x, v1.x));
        pk.y = h2u(__floats2half2_rn(v0.y, v1.y));
        pk.z = h2u(__floats2half2_rn(v0.z, v1.z));
        pk.w = h2u(__floats2half2_rn(v0.w, v1.w));
        *reinterpret_cast<uint4*>(&sB[r * BS_STRIDE + q * 4]) = pk;
    }

    // ---- prefetch first A tile into regs (as half2) ----
    int mt = blockIdx.x;
    uint32_t stage[16];
    {
        int m0 = mt * 128;
#pragma unroll
        for (int j = 0; j < 8; j++) {
            int i = tid + j * 512;
            int r = i >> 5, q = i & 31;
            int row = m0 + r;
            float4 v = make_float4(0.f, 0.f, 0.f, 0.f);
            if (row < N_NODES)
                v = FIRST ? A4[(size_t)row * NQUAD + q] : g_buf[(size_t)row * NQUAD + q];
            stage[j * 2    ] = h2u(__floats2half2_rn(v.x, v.y));
            stage[j * 2 + 1] = h2u(__floats2half2_rn(v.z, v.w));
        }
    }

    int buf = 0;
    while (mt < NTILES) {
        const int m0 = mt * 128;
        // ---- store staged A tile to smem buffer ----
        __half2* A = sA + buf * AS_ELEMS;
#pragma unroll
        for (int j = 0; j < 8; j++) {
            int i = tid + j * 512;
            int r = i >> 5, q = i & 31;
            uint2 p = make_uint2(stage[j * 2], stage[j * 2 + 1]);
            *reinterpret_cast<uint2*>(&A[r * AS_STRIDE + q * 2]) = p;
        }
        __syncthreads();

        // ---- prefetch next tile while computing ----
        const int mnext = mt + GEMM_GRID;
        if (mnext < NTILES) {
            int m0n = mnext * 128;
#pragma unroll
            for (int j = 0; j < 8; j++) {
                int i = tid + j * 512;
                int r = i >> 5, q = i & 31;
                int row = m0n + r;
                float4 v = make_float4(0.f, 0.f, 0.f, 0.f);
                if (row < N_NODES)
                    v = FIRST ? A4[(size_t)row * NQUAD + q] : g_buf[(size_t)row * NQUAD + q];
                stage[j * 2    ] = h2u(__floats2half2_rn(v.x, v.y));
                stage[j * 2 + 1] = h2u(__floats2half2_rn(v.z, v.w));
            }
        }

        // ---- compute: 8 k16 chunks ----
        float acc[2][4][4] = {};
#pragma unroll
        for (int c = 0; c < 8; c++) {
            const int h2 = c * 8;                // half2 (A) / kpair (B) base
            uint32_t af[2][4];
#pragma unroll
            for (int fm = 0; fm < 2; fm++) {
                int rb = wm * 32 + fm * 16 + gid;
                const __half2* ar0 = &A[rb * AS_STRIDE];
                const __half2* ar1 = &A[(rb + 8) * AS_STRIDE];
                af[fm][0] = h2u(ar0[h2 + tig]);
                af[fm][1] = h2u(ar1[h2 + tig]);
                af[fm][2] = h2u(ar0[h2 + tig + 4]);
                af[fm][3] = h2u(ar1[h2 + tig + 4]);
            }
#pragma unroll
            for (int fn = 0; fn < 4; fn++) {
                int cn = wn * 32 + fn * 8 + gid;
                uint32_t b0 = h2u(sB[(h2 + tig    ) * BS_STRIDE + cn]);
                uint32_t b1 = h2u(sB[(h2 + tig + 4) * BS_STRIDE + cn]);
                mma_f16(acc[0][fn], af[0], b0, b1);
                mma_f16(acc[1][fn], af[1], b0, b1);
            }
        }

        // ---- epilogue: scale by dinv, store fp16 ----
#pragma unroll
        for (int fm = 0; fm < 2; fm++) {
            int r0 = m0 + wm * 32 + fm * 16 + gid;
            int r1 = r0 + 8;
            float d0 = (r0 < N_NODES) ? g_dinv[r0] : 0.f;
            float d1 = (r1 < N_NODES) ? g_dinv[r1] : 0.f;
#pragma unroll
            for (int fn = 0; fn < 4; fn++) {
                int h2i = wn * 16 + fn * 4 + tig;
                if (r0 < N_NODES)
                    g_h[(size_t)r0 * 64 + h2i] =
                        __floats2half2_rn(acc[fm][fn][0] * d0, acc[fm][fn][1] * d0);
                if (r1 < N_NODES)
                    g_h[(size_t)r1 * 64 + h2i] =
                        __floats2half2_rn(acc[fm][fn][2] * d1, acc[fm][fn][3] * d1);
            }
        }

        mt = mnext;
        buf ^= 1;
    }
}

// ---------------- aggregation: warp per node, fp16 rows, fp32 accumulate ----------
// out[d] = relu( dinv[d] * (g[d] + sum_{s in N(d)} g[s]) + b )
template <bool LAST>
__global__ __launch_bounds__(256) void k_agg(const float* __restrict__ bias,
                                             float* __restrict__ outExt) {
    int gw   = (blockIdx.x * blockDim.x + threadIdx.x) >> 5;
    int lane = threadIdx.x & 31;
    if (gw >= N_NODES) return;

    const uint2* H = reinterpret_cast<const uint2*>(g_h);   // 32 uint2 per row

    float4 acc;
    {
        uint2 u = H[(size_t)gw * 32 + lane];                // self-loop term
        float2 f0 = __half22float2(*reinterpret_cast<__half2*>(&u.x));
        float2 f1 = __half22float2(*reinterpret_cast<__half2*>(&u.y));
        acc = make_float4(f0.x, f0.y, f1.x, f1.y);
    }
    const int beg = g_rowptr[gw], end = g_rowptr[gw + 1];

    for (int j = beg; j < end; j += 32) {
        int jl  = j + lane;
        int idx = (jl < end) ? g_col[jl] : 0;
        int cnt = min(32, end - j);
        int t = 0;
        for (; t + 8 <= cnt; t += 8) {           // 8 independent gathers in flight
            uint2 v[8];
#pragma unroll
            for (int u = 0; u < 8; u++) {
                int s = __shfl_sync(0xffffffffu, idx, t + u);
                v[u] = H[(size_t)s * 32 + lane];
            }
#pragma unroll
            for (int u = 0; u < 8; u++) {
                float2 f0 = __half22float2(*reinterpret_cast<__half2*>(&v[u].x));
                float2 f1 = __half22float2(*reinterpret_cast<__half2*>(&v[u].y));
                acc.x += f0.x; acc.y += f0.y; acc.z += f1.x; acc.w += f1.y;
            }
        }
        for (; t < cnt; t++) {
            int s = __shfl_sync(0xffffffffu, idx, t);
            uint2 u = H[(size_t)s * 32 + lane];
            float2 f0 = __half22float2(*reinterpret_cast<__half2*>(&u.x));
            float2 f1 = __half22float2(*reinterpret_cast<__half2*>(&u.y));
            acc.x += f0.x; acc.y += f0.y; acc.z += f1.x; acc.w += f1.y;
        }
    }

    float dv  = g_dinv[gw];
    float4 bb = reinterpret_cast<const float4*>(bias)[lane];
    float4 o;
    o.x = fmaxf(acc.x * dv + bb.x, 0.f);
    o.y = fmaxf(acc.y * dv + bb.y, 0.f);
    o.z = fmaxf(acc.z * dv + bb.z, 0.f);
    o.w = fmaxf(acc.w * dv + bb.w, 0.f);
    if (LAST) {
        reinterpret_cast<float4*>(outExt)[(size_t)gw * NQUAD + lane] = o;
    } else {
        g_buf[(size_t)gw * NQUAD + lane] = o;
    }
}

// ---------------- launch ----------------
extern "C" void kernel_launch(void* const* d_in, const int* in_sizes, int n_in,
                              void* d_out, int out_size) {
    const float* x  = (const float*)d_in[0];
    const int*   ei = (const int*)d_in[1];          // int32 edge_index
    const float* W0 = (const float*)d_in[2];
    const float* b0 = (const float*)d_in[3];
    const float* W1 = (const float*)d_in[4];
    const float* b1 = (const float*)d_in[5];
    const float* W2 = (const float*)d_in[6];
    const float* b2 = (const float*)d_in[7];
    float* out = (float*)d_out;

    const int nodeBlocks = (N_NODES + 255) / 256;
    const int edgeBlocks = (N_EDGES + 255) / 256;
    const int scanBlocks = (N_NODES + 1023) / 1024;   // 98
    const int aggBlocks  = (N_NODES * 32 + 255) / 256;

    cudaFuncSetAttribute(k_gemm_f16<true>,
                         cudaFuncAttributeMaxDynamicSharedMemorySize, SMEM_GEMM);
    cudaFuncSetAttribute(k_gemm_f16<false>,
                         cudaFuncAttributeMaxDynamicSharedMemorySize, SMEM_GEMM);

    // CSR build (recomputed every call: deterministic work)
    k_zero_deg<<<nodeBlocks, 256>>>();
    k_hist<<<edgeBlocks, 256>>>(ei);
    k_scan1<<<scanBlocks, 1024>>>();
    k_scan2<<<1, 128>>>(scanBlocks);
    k_scan3<<<nodeBlocks, 256>>>();
    k_scatter<<<edgeBlocks, 256>>>(ei);

    // layer 0
    k_gemm_f16<true ><<<GEMM_GRID, 512, SMEM_GEMM>>>(x, W0);
    k_agg     <false><<<aggBlocks, 256>>>(b0, nullptr);
    // layer 1
    k_gemm_f16<false><<<GEMM_GRID, 512, SMEM_GEMM>>>(nullptr, W1);
    k_agg     <false><<<aggBlocks, 256>>>(b1, nullptr);
    // layer 2
    k_gemm_f16<false><<<GEMM_GRID, 512, SMEM_GEMM>>>(nullptr, W2);
    k_agg     <true ><<<aggBlocks, 256>>>(b2, out);
}